// round 14
// baseline (speedup 1.0000x reference)
#include <cuda_runtime.h>
#include <cstddef>

// NNUE evaluator, split into two kernels:
//   K1: pure gather (one position per block, no smem, no barriers)
//   K2: layer 1-3 MLP reading feat back from L2
// d_in: 0 white_idx [B,32] (int32/int64 runtime detected)  1 black_idx
//       2 w_ft [45056,512] f32  3 b_ft[512]  4 w1[1024,32] 5 b1[32]
//       6 w2[32,32] 7 b2[32] 8 w3[32,1] 9 b3[1]
// d_out: features [B,1024] f32 followed by values [B] f32.

#define F_DIM    45056
#define NC4      128          // float4 per 512-wide perspective row
#define NFEAT    1024
#define NACT     32
#define H1       32
#define PB       16
#define PH       8
#define X1S      33
#define NTHR     256

// scratch: transposed w1 [32][1024]
__device__ __align__(16) float g_w1t[H1 * NFEAT];

// K2 smem: feat PB*1024 + w2s 1024 + x1s PB*33 + biases 96
#define SMEM_FLOATS (PB*NFEAT + 1024 + PB*X1S + 96)
#define SMEM_BYTES  (SMEM_FLOATS * 4)

// ---- prep: transpose w1 [1024,32] -> g_w1t [32][1024] ----
__global__ void w1_transpose_kernel(const float* __restrict__ w1)
{
    const int e = blockIdx.x * blockDim.x + threadIdx.x;
    if (e < NFEAT * H1)
        g_w1t[(e & 31) * NFEAT + (e >> 5)] = w1[e];
}

// ---- K1: gather. One position per 256-thread block.
//      warp w: side = w>>2, colgroup = w&3; col = colgroup*32 + lane. ----
__global__ __launch_bounds__(NTHR)
void gather_kernel(const void* __restrict__ widx_raw,
                   const void* __restrict__ bidx_raw,
                   const float* __restrict__ w_ft,
                   const float* __restrict__ b_ft,
                   float* __restrict__ out_feat)
{
    const int pos  = blockIdx.x;
    const int tid  = threadIdx.x;
    const int lane = tid & 31;
    const int wid  = tid >> 5;
    const int side = wid >> 2;          // 0 white, 1 black
    const int col  = (wid & 3) * 32 + lane;   // float4 column 0..127

    const int is64 = (__ldg((const int*)widx_raw + 1) == 0) ? 1 : 0;

    // each lane loads one of this side's 32 indices (coalesced), premul by NC4
    const void* ip = side ? bidx_raw : widx_raw;
    int idx;
    if (is64) idx = (int)((const long long*)ip)[(size_t)pos * NACT + lane];
    else      idx = ((const int*)ip)[(size_t)pos * NACT + lane];
    idx *= NC4;

    const float4* __restrict__ wft4 = (const float4*)w_ft;
    float4 acc = ((const float4*)b_ft)[col];

    #pragma unroll
    for (int a0 = 0; a0 < NACT; a0 += 8) {
        int r[8];
        #pragma unroll
        for (int u = 0; u < 8; u++)
            r[u] = __shfl_sync(0xffffffffu, idx, a0 + u);
        float4 v[8];
        #pragma unroll
        for (int u = 0; u < 8; u++)
            v[u] = __ldcg(wft4 + r[u] + col);
        #pragma unroll
        for (int u = 0; u < 8; u++) {
            acc.x += v[u].x; acc.y += v[u].y;
            acc.z += v[u].z; acc.w += v[u].w;
        }
    }
    acc.x = fmaxf(acc.x, 0.f); acc.y = fmaxf(acc.y, 0.f);
    acc.z = fmaxf(acc.z, 0.f); acc.w = fmaxf(acc.w, 0.f);

    // normal (write-back) store: K2 re-reads this from L2
    ((float4*)out_feat)[(size_t)pos * 256 + side * 128 + col] = acc;
}

// ---- K2: layers 1-3. feat read back from gmem (L2-resident). ----
__global__ __launch_bounds__(NTHR, 2)
void mlp_kernel(const float* __restrict__ featg,
                const float* __restrict__ b1,
                const float* __restrict__ w2,
                const float* __restrict__ b2,
                const float* __restrict__ w3,
                const float* __restrict__ b3,
                float* __restrict__ out_val,
                int Bn)
{
    extern __shared__ float smem[];
    float* feat = smem;                         // PB*1024
    float* w2s  = feat + PB*NFEAT;              // 1024
    float* x1s  = w2s + 1024;                   // PB*33
    float* b1s  = x1s + PB*X1S;                 // 32
    float* b2s  = b1s + 32;                     // 32
    float* w3s  = b2s + 32;                     // 32

    const int tid  = threadIdx.x;
    const int lane = tid & 31;
    const int wid  = tid >> 5;

    for (int e = tid; e < H1 * H1; e += NTHR) w2s[e] = w2[e];
    if (tid < 32) {
        b1s[tid] = b1[tid];
        b2s[tid] = b2[tid];
        w3s[tid] = w3[tid];
    }
    const float b3v = __ldg(b3);

    // contiguous position range per block
    const int grid = gridDim.x;
    const int base = Bn / grid, rem = Bn % grid;
    const int bid  = blockIdx.x;
    int start, count;
    if (bid < rem) { count = base + 1; start = bid * count; }
    else           { count = base;     start = rem * (base + 1) + (bid - rem) * base; }

    __syncthreads();

    for (int off = 0; off < count; off += PB) {
        const int pos0 = start + off;
        const int npos = (count - off < PB) ? (count - off) : PB;

        // ---- stream feat batch from gmem (L2 hits) into smem ----
        {
            const float4* __restrict__ src = (const float4*)(featg + (size_t)pos0 * NFEAT);
            float4* __restrict__ dst = (float4*)feat;
            const int n4 = npos * 256;
            for (int e = tid; e < n4; e += NTHR)
                dst[e] = __ldcg(src + e);
        }
        __syncthreads();

        // ---- layer 1: warp w owns outputs 4w..4w+3; passes of PH positions ----
        {
            const int j0 = wid * 4;
            const float* __restrict__ r0 = g_w1t + (j0 + 0) * NFEAT;
            const float* __restrict__ r1 = g_w1t + (j0 + 1) * NFEAT;
            const float* __restrict__ r2 = g_w1t + (j0 + 2) * NFEAT;
            const float* __restrict__ r3 = g_w1t + (j0 + 3) * NFEAT;

            for (int pbase = 0; pbase < npos; pbase += PH) {
                float acc0[PH], acc1[PH], acc2[PH], acc3[PH];
                #pragma unroll
                for (int pp = 0; pp < PH; pp++) { acc0[pp]=0.f; acc1[pp]=0.f; acc2[pp]=0.f; acc3[pp]=0.f; }

                #pragma unroll
                for (int kk = 0; kk < 8; kk++) {        // i-chunks of 128
                    float wr0[4], wr1[4], wr2[4], wr3[4];
                    #pragma unroll
                    for (int k = 0; k < 4; k++) {
                        const int i = lane + 32 * (4 * kk + k);
                        wr0[k] = __ldg(r0 + i);
                        wr1[k] = __ldg(r1 + i);
                        wr2[k] = __ldg(r2 + i);
                        wr3[k] = __ldg(r3 + i);
                    }
                    #pragma unroll
                    for (int pp = 0; pp < PH; pp++) {
                        const int p = pbase + pp;
                        if (p < npos) {
                            #pragma unroll
                            for (int k = 0; k < 4; k++) {
                                const float f = feat[p * NFEAT + lane + 32 * (4 * kk + k)];
                                acc0[pp] = fmaf(f, wr0[k], acc0[pp]);
                                acc1[pp] = fmaf(f, wr1[k], acc1[pp]);
                                acc2[pp] = fmaf(f, wr2[k], acc2[pp]);
                                acc3[pp] = fmaf(f, wr3[k], acc3[pp]);
                            }
                        }
                    }
                }
                #pragma unroll
                for (int pp = 0; pp < PH; pp++) {
                    const int p = pbase + pp;
                    if (p < npos) {
                        float s0 = acc0[pp], s1 = acc1[pp], s2 = acc2[pp], s3 = acc3[pp];
                        #pragma unroll
                        for (int o = 16; o; o >>= 1) {
                            s0 += __shfl_xor_sync(0xffffffffu, s0, o);
                            s1 += __shfl_xor_sync(0xffffffffu, s1, o);
                            s2 += __shfl_xor_sync(0xffffffffu, s2, o);
                            s3 += __shfl_xor_sync(0xffffffffu, s3, o);
                        }
                        if (lane == 0) {
                            x1s[p * X1S + j0 + 0] = fmaxf(s0 + b1s[j0 + 0], 0.f);
                            x1s[p * X1S + j0 + 1] = fmaxf(s1 + b1s[j0 + 1], 0.f);
                            x1s[p * X1S + j0 + 2] = fmaxf(s2 + b1s[j0 + 2], 0.f);
                            x1s[p * X1S + j0 + 3] = fmaxf(s3 + b1s[j0 + 3], 0.f);
                        }
                    }
                }
            }
        }
        __syncthreads();

        // ---- layers 2+3: one warp per position ----
        for (int p = wid; p < npos; p += 8) {
            float s = b2s[lane];
            #pragma unroll
            for (int i = 0; i < H1; i++)
                s = fmaf(x1s[p * X1S + i], w2s[i * H1 + lane], s);
            s = fmaxf(s, 0.f);
            float v = s * w3s[lane];
            #pragma unroll
            for (int o = 16; o; o >>= 1)
                v += __shfl_xor_sync(0xffffffffu, v, o);
            if (lane == 0)
                __stcs(out_val + pos0 + p, (v + b3v) * 100.0f);
        }
        __syncthreads();
    }
}

extern "C" void kernel_launch(void* const* d_in, const int* in_sizes, int n_in,
                              void* d_out, int out_size)
{
    (void)n_in; (void)out_size;
    const void*  widx = d_in[0];
    const void*  bidx = d_in[1];
    const float* w_ft = (const float*)d_in[2];
    const float* b_ft = (const float*)d_in[3];
    const float* w1   = (const float*)d_in[4];
    const float* b1   = (const float*)d_in[5];
    const float* w2   = (const float*)d_in[6];
    const float* b2   = (const float*)d_in[7];
    const float* w3   = (const float*)d_in[8];
    const float* b3   = (const float*)d_in[9];

    const int Bn = in_sizes[0] / NACT;

    float* out_feat = (float*)d_out;
    float* out_val  = out_feat + (size_t)Bn * NFEAT;

    cudaFuncSetAttribute(mlp_kernel,
                         cudaFuncAttributeMaxDynamicSharedMemorySize,
                         SMEM_BYTES);

    int dev = 0, nsm = 148;
    cudaGetDevice(&dev);
    cudaDeviceGetAttribute(&nsm, cudaDevAttrMultiProcessorCount, dev);
    if (nsm <= 0) nsm = 148;

    w1_transpose_kernel<<<(NFEAT * H1 + 255) / 256, 256>>>(w1);

    gather_kernel<<<Bn, NTHR>>>(widx, bidx, w_ft, b_ft, out_feat);

    int grid2 = nsm * 2;
    if (grid2 > Bn) grid2 = Bn;
    mlp_kernel<<<grid2, NTHR, SMEM_BYTES>>>(
        out_feat, b1, w2, b2, w3, b3, out_val, Bn);
}